// round 10
// baseline (speedup 1.0000x reference)
#include <cuda_runtime.h>
#include <cuda_bf16.h>

// Problem constants
#define BATCH   4
#define SEQ     2048
#define DMODEL  1024
#define NHEADS  16
#define HDIM    64
#define MROWS   (BATCH * SEQ)          // 8192
#define ELEMS   (MROWS * DMODEL)       // 8388608

// Scratch: Q, K, V, heads  (row-major [M, D]; D index = h*64 + hd)
__device__ float g_q[ELEMS];
__device__ float g_k[ELEMS];
__device__ float g_v[ELEMS];
__device__ float g_h[ELEMS];

// ---------------------------------------------------------------------------
// SGEMM + bias: C[M,1024] = A[M,1024] * B[1024,1024] + bias
// 128x128 block tile, BK=8, 256 threads, 8x8 per-thread microtile.
// ---------------------------------------------------------------------------
__global__ __launch_bounds__(256, 2)
void sgemm_bias_kernel(const float* __restrict__ A, const float* __restrict__ B,
                       const float* __restrict__ bias, float* __restrict__ C)
{
    const int K = 1024, N = 1024;
    __shared__ float As[8 * 128];   // As[k][m]
    __shared__ float Bs[8 * 128];   // Bs[k][n]

    const int t  = threadIdx.x;
    const int bm = blockIdx.y * 128;
    const int bn = blockIdx.x * 128;

    const int arow = t >> 1;          // 0..127
    const int acol = (t & 1) << 2;    // 0 or 4
    const int brow = t >> 5;          // 0..7
    const int bcol = (t & 31) << 2;   // 0..124
    const int ty = t >> 4, tx = t & 15;

    float acc[8][8];
#pragma unroll
    for (int i = 0; i < 8; i++)
#pragma unroll
        for (int j = 0; j < 8; j++) acc[i][j] = 0.f;

    const float* Aptr = A + (bm + arow) * K + acol;
    const float* Bptr = B + brow * N + bn + bcol;

    for (int k0 = 0; k0 < K; k0 += 8) {
        float4 a = *(const float4*)(Aptr + k0);
        float4 b = *(const float4*)(Bptr + k0 * N);
        __syncthreads();
        As[(acol + 0) * 128 + arow] = a.x;
        As[(acol + 1) * 128 + arow] = a.y;
        As[(acol + 2) * 128 + arow] = a.z;
        As[(acol + 3) * 128 + arow] = a.w;
        *(float4*)&Bs[brow * 128 + bcol] = b;
        __syncthreads();
#pragma unroll
        for (int kk = 0; kk < 8; kk++) {
            float4 a0 = *(float4*)&As[kk * 128 + ty * 8];
            float4 a1 = *(float4*)&As[kk * 128 + ty * 8 + 4];
            float4 b0 = *(float4*)&Bs[kk * 128 + tx * 8];
            float4 b1 = *(float4*)&Bs[kk * 128 + tx * 8 + 4];
            float ar[8] = {a0.x, a0.y, a0.z, a0.w, a1.x, a1.y, a1.z, a1.w};
            float br[8] = {b0.x, b0.y, b0.z, b0.w, b1.x, b1.y, b1.z, b1.w};
#pragma unroll
            for (int i = 0; i < 8; i++)
#pragma unroll
                for (int j = 0; j < 8; j++)
                    acc[i][j] = fmaf(ar[i], br[j], acc[i][j]);
        }
    }

#pragma unroll
    for (int i = 0; i < 8; i++) {
        int row = bm + ty * 8 + i;
#pragma unroll
        for (int j0 = 0; j0 < 8; j0 += 4) {
            int col = bn + tx * 8 + j0;
            float4 c;
            c.x = acc[i][j0 + 0] + bias[col + 0];
            c.y = acc[i][j0 + 1] + bias[col + 1];
            c.z = acc[i][j0 + 2] + bias[col + 2];
            c.w = acc[i][j0 + 3] + bias[col + 3];
            *(float4*)&C[row * N + col] = c;
        }
    }
}

// ---------------------------------------------------------------------------
// Flash attention: one block handles (b,h) and 64 query rows.
// Br = Bc = 64, Hd = 64. Online softmax, O accumulated in registers.
// Smem (dynamic, 68608 B):
//   Qt[64 d][68] transposed Q tile (stride 68: 16B-aligned + bank rotation)
//   Kt[64 d][68] transposed K tile
//   Vs[64 k][64 c]
//   Ss[64 r][65]  scores/probs (pad 65 -> conflict-free row scans)
//   m_s/l_s/al_s[64] row stats
// ---------------------------------------------------------------------------
#define QT_STRIDE 68
#define FLASH_SMEM_FLOATS (64*QT_STRIDE*2 + 64*64 + 64*65 + 3*64)
#define FLASH_SMEM_BYTES  (FLASH_SMEM_FLOATS * 4)

__global__ __launch_bounds__(256, 2)
void flash_attn_kernel(const float* __restrict__ Q, const float* __restrict__ Kg,
                       const float* __restrict__ Vg, float* __restrict__ O)
{
    extern __shared__ float sm[];
    float* Qt   = sm;                        // 64*68
    float* Kt   = Qt + 64 * QT_STRIDE;       // 64*68
    float* Vs   = Kt + 64 * QT_STRIDE;       // 64*64
    float* Ss   = Vs + 64 * 64;              // 64*65
    float* m_s  = Ss + 64 * 65;
    float* l_s  = m_s + 64;
    float* al_s = l_s + 64;

    const int t  = threadIdx.x;
    const int qb = blockIdx.x * 64;
    const int bh = blockIdx.y;               // b*16 + h
    const int b  = bh >> 4;
    const int h  = bh & 15;
    const float scale = 0.125f;              // 1/sqrt(64)

    const int tx = t & 15, ty = t >> 4;
    const int iq0 = tx * 4, jk0 = ty * 4;    // QK^T microtile
    const int r0  = ty * 4, c0  = tx * 4;    // PV / O microtile

    // Load Q tile transposed: Qt[d][i]
    const float* Qbase = Q + (b * SEQ + qb) * DMODEL + h * HDIM;
    for (int e = t * 4; e < 64 * 64; e += 1024) {
        int i = e >> 6, d = e & 63;
        float4 v = *(const float4*)&Qbase[i * DMODEL + d];
        Qt[(d + 0) * QT_STRIDE + i] = v.x;
        Qt[(d + 1) * QT_STRIDE + i] = v.y;
        Qt[(d + 2) * QT_STRIDE + i] = v.z;
        Qt[(d + 3) * QT_STRIDE + i] = v.w;
    }
    if (t < 64) { m_s[t] = -1e30f; l_s[t] = 0.f; }

    float o[4][4];
#pragma unroll
    for (int i = 0; i < 4; i++)
#pragma unroll
        for (int j = 0; j < 4; j++) o[i][j] = 0.f;

    for (int kb = 0; kb < SEQ; kb += 64) {
        __syncthreads();   // previous tile's Ss/Vs reads complete

        // Load K (transposed) and V tiles
        const float* Kbase = Kg + (b * SEQ + kb) * DMODEL + h * HDIM;
        const float* Vbase = Vg + (b * SEQ + kb) * DMODEL + h * HDIM;
        for (int e = t * 4; e < 64 * 64; e += 1024) {
            int j = e >> 6, d = e & 63;
            float4 v = *(const float4*)&Kbase[j * DMODEL + d];
            Kt[(d + 0) * QT_STRIDE + j] = v.x;
            Kt[(d + 1) * QT_STRIDE + j] = v.y;
            Kt[(d + 2) * QT_STRIDE + j] = v.z;
            Kt[(d + 3) * QT_STRIDE + j] = v.w;
            float4 w = *(const float4*)&Vbase[j * DMODEL + d];
            *(float4*)&Vs[j * 64 + d] = w;
        }
        __syncthreads();

        // S = Q * K^T (scaled), microtile 4x4 per thread
        float s[4][4];
#pragma unroll
        for (int i = 0; i < 4; i++)
#pragma unroll
            for (int j = 0; j < 4; j++) s[i][j] = 0.f;
#pragma unroll 8
        for (int d = 0; d < 64; d++) {
            float4 qv = *(float4*)&Qt[d * QT_STRIDE + iq0];
            float4 kv = *(float4*)&Kt[d * QT_STRIDE + jk0];
            float qa[4] = {qv.x, qv.y, qv.z, qv.w};
            float ka[4] = {kv.x, kv.y, kv.z, kv.w};
#pragma unroll
            for (int i = 0; i < 4; i++)
#pragma unroll
                for (int j = 0; j < 4; j++)
                    s[i][j] = fmaf(qa[i], ka[j], s[i][j]);
        }
#pragma unroll
        for (int i = 0; i < 4; i++)
#pragma unroll
            for (int j = 0; j < 4; j++)
                Ss[(iq0 + i) * 65 + jk0 + j] = s[i][j] * scale;
        __syncthreads();

        // Online softmax: one thread per row (pad-65 => conflict-free scan)
        if (t < 64) {
            float* row = Ss + t * 65;
            float mo = m_s[t], mn = mo;
#pragma unroll 8
            for (int j = 0; j < 64; j++) mn = fmaxf(mn, row[j]);
            float al = __expf(mo - mn);
            float ls = 0.f;
#pragma unroll 8
            for (int j = 0; j < 64; j++) {
                float p = __expf(row[j] - mn);
                row[j] = p;
                ls += p;
            }
            m_s[t]  = mn;
            l_s[t]  = l_s[t] * al + ls;
            al_s[t] = al;
        }
        __syncthreads();

        // Rescale O, then O += P * V
#pragma unroll
        for (int i = 0; i < 4; i++) {
            float al = al_s[r0 + i];
            o[i][0] *= al; o[i][1] *= al; o[i][2] *= al; o[i][3] *= al;
        }
#pragma unroll 8
        for (int k = 0; k < 64; k++) {
            float4 vv = *(float4*)&Vs[k * 64 + c0];
#pragma unroll
            for (int i = 0; i < 4; i++) {
                float p = Ss[(r0 + i) * 65 + k];
                o[i][0] = fmaf(p, vv.x, o[i][0]);
                o[i][1] = fmaf(p, vv.y, o[i][1]);
                o[i][2] = fmaf(p, vv.z, o[i][2]);
                o[i][3] = fmaf(p, vv.w, o[i][3]);
            }
        }
    }

    // Epilogue: normalize by l and store heads in [B,S,H*Hd] row-major
    float* Obase = O + (b * SEQ + qb) * DMODEL + h * HDIM;
#pragma unroll
    for (int i = 0; i < 4; i++) {
        float inv = 1.f / l_s[r0 + i];
        float4 out;
        out.x = o[i][0] * inv;
        out.y = o[i][1] * inv;
        out.z = o[i][2] * inv;
        out.w = o[i][3] * inv;
        *(float4*)&Obase[(r0 + i) * DMODEL + c0] = out;
    }
}

// ---------------------------------------------------------------------------
extern "C" void kernel_launch(void* const* d_in, const int* in_sizes, int n_in,
                              void* d_out, int out_size)
{
    (void)in_sizes; (void)n_in; (void)out_size;
    const float* x  = (const float*)d_in[0];
    const float* Wq = (const float*)d_in[1];
    const float* bq = (const float*)d_in[2];
    const float* Wk = (const float*)d_in[3];
    const float* bk = (const float*)d_in[4];
    const float* Wv = (const float*)d_in[5];
    const float* bv = (const float*)d_in[6];
    const float* Wo = (const float*)d_in[7];
    const float* bo = (const float*)d_in[8];
    float* out = (float*)d_out;

    float *gq, *gk, *gv, *gh;
    cudaGetSymbolAddress((void**)&gq, g_q);
    cudaGetSymbolAddress((void**)&gk, g_k);
    cudaGetSymbolAddress((void**)&gv, g_v);
    cudaGetSymbolAddress((void**)&gh, g_h);

    dim3 ggrid(DMODEL / 128, MROWS / 128);   // (8, 64)
    sgemm_bias_kernel<<<ggrid, 256>>>(x, Wq, bq, gq);
    sgemm_bias_kernel<<<ggrid, 256>>>(x, Wk, bk, gk);
    sgemm_bias_kernel<<<ggrid, 256>>>(x, Wv, bv, gv);

    cudaFuncSetAttribute(flash_attn_kernel,
                         cudaFuncAttributeMaxDynamicSharedMemorySize,
                         FLASH_SMEM_BYTES);
    flash_attn_kernel<<<dim3(SEQ / 64, BATCH * NHEADS), 256, FLASH_SMEM_BYTES>>>(
        gq, gk, gv, gh);

    sgemm_bias_kernel<<<ggrid, 256>>>(gh, Wo, bo, out);
}